// round 15
// baseline (speedup 1.0000x reference)
#include <cuda_runtime.h>

#define NPTS 16384
#define MTOT 8192
#define M1   4096
#define CIN  64
#define COUT 128
#define KNNK 16
#define CF   67   // 3 + 64

// ---- output layout (floats) ----
#define OFF_NP1 0
#define OFF_X1  12288
#define OFF_NO1 536576
#define OFF_NP2 536577
#define OFF_X2  548865
#define OFF_NO2 1073153

// ---- device scratch (no allocations allowed) ----
__device__ int   g_idx[MTOT];
__device__ int   g_knn[MTOT * KNNK];
__device__ float g_h[(size_t)MTOT * KNNK * COUT];   // 64 MB
__device__ float g_scale[2 * COUT];
__device__ float g_shift[2 * COUT];
// sorted point arrays (Morton order)
__device__ float g_sx[NPTS];
__device__ float g_sy[NPTS];
__device__ float g_sz[NPTS];
__device__ unsigned g_sopack[NPTS];   // (orig_idx << 14) | sorted_pos
// BN partial sums
__device__ float g_part1[128 * 128];
__device__ float g_part2[128 * 128];

// ============================================================
// no-op dummy — keeps the ncu -s 5 capture window on fps_kernel
// ============================================================
__global__ void dummy_kernel() {}

// ============================================================
// 0. Morton sort — single CTA bitonic sort of (code<<14 | idx)
// ============================================================
__device__ __forceinline__ unsigned expand10(unsigned v)
{
    v &= 1023u;
    v = (v | (v << 16)) & 0x030000FFu;
    v = (v | (v << 8))  & 0x0300F00Fu;
    v = (v | (v << 4))  & 0x030C30C3u;
    v = (v | (v << 2))  & 0x09249249u;
    return v;
}

__global__ void __launch_bounds__(1024, 1)
sort_kernel(const float* __restrict__ p)
{
    extern __shared__ unsigned long long key[];   // 16384 * 8B = 128KB
    __shared__ float rmin[3][32], rmax[3][32];
    __shared__ float bb[6];

    int tid = threadIdx.x, lane = tid & 31, wid = tid >> 5;

    float mn[3] = {1e30f, 1e30f, 1e30f};
    float mx[3] = {-1e30f, -1e30f, -1e30f};
    for (int i = tid; i < NPTS; i += 1024) {
        float c[3] = {p[3 * i], p[3 * i + 1], p[3 * i + 2]};
        #pragma unroll
        for (int d = 0; d < 3; d++) {
            mn[d] = fminf(mn[d], c[d]);
            mx[d] = fmaxf(mx[d], c[d]);
        }
    }
    #pragma unroll
    for (int off = 16; off > 0; off >>= 1) {
        #pragma unroll
        for (int d = 0; d < 3; d++) {
            mn[d] = fminf(mn[d], __shfl_xor_sync(0xffffffffu, mn[d], off));
            mx[d] = fmaxf(mx[d], __shfl_xor_sync(0xffffffffu, mx[d], off));
        }
    }
    if (lane == 0) {
        #pragma unroll
        for (int d = 0; d < 3; d++) { rmin[d][wid] = mn[d]; rmax[d][wid] = mx[d]; }
    }
    __syncthreads();
    if (tid < 32) {
        #pragma unroll
        for (int d = 0; d < 3; d++) { mn[d] = rmin[d][tid]; mx[d] = rmax[d][tid]; }
        #pragma unroll
        for (int off = 16; off > 0; off >>= 1) {
            #pragma unroll
            for (int d = 0; d < 3; d++) {
                mn[d] = fminf(mn[d], __shfl_xor_sync(0xffffffffu, mn[d], off));
                mx[d] = fmaxf(mx[d], __shfl_xor_sync(0xffffffffu, mx[d], off));
            }
        }
        if (tid == 0) {
            #pragma unroll
            for (int d = 0; d < 3; d++) { bb[d] = mn[d]; bb[3 + d] = mx[d]; }
        }
    }
    __syncthreads();

    float ox = bb[0], oy = bb[1], oz = bb[2];
    float scx = 1023.0f / fmaxf(bb[3] - bb[0], 1e-20f);
    float scy = 1023.0f / fmaxf(bb[4] - bb[1], 1e-20f);
    float scz = 1023.0f / fmaxf(bb[5] - bb[2], 1e-20f);

    for (int i = tid; i < NPTS; i += 1024) {
        unsigned xi = (unsigned)fminf(fmaxf((p[3 * i]     - ox) * scx, 0.f), 1023.f);
        unsigned yi = (unsigned)fminf(fmaxf((p[3 * i + 1] - oy) * scy, 0.f), 1023.f);
        unsigned zi = (unsigned)fminf(fmaxf((p[3 * i + 2] - oz) * scz, 0.f), 1023.f);
        unsigned code = (expand10(xi) << 2) | (expand10(yi) << 1) | expand10(zi);
        key[i] = ((unsigned long long)code << 14) | (unsigned)i;
    }
    __syncthreads();

    // bitonic sort
    for (int k = 2; k <= NPTS; k <<= 1) {
        for (int j = k >> 1; j > 0; j >>= 1) {
            for (int t = tid; t < NPTS; t += 1024) {
                int ixj = t ^ j;
                if (ixj > t) {
                    bool up = ((t & k) == 0);
                    unsigned long long a = key[t], b = key[ixj];
                    if ((a > b) == up) { key[t] = b; key[ixj] = a; }
                }
            }
            __syncthreads();
        }
    }

    for (int i = tid; i < NPTS; i += 1024) {
        int oi = (int)(key[i] & 16383ull);
        g_sx[i] = p[3 * oi];
        g_sy[i] = p[3 * oi + 1];
        g_sz[i] = p[3 * oi + 2];
        g_sopack[i] = ((unsigned)oi << 14) | (unsigned)i;
    }
}

// ============================================================
// 1. FPS — single CTA, 512 threads, ONE 32-point Morton chunk
//    per thread, bbox skipping, u64-key dirty-pass argmax (R14).
//    R15: paired SMEM layout — xy of slot pairs in float4
//    (LDS.128) and z pairs in float2 (LDS.64): 2 issues / 2 pts.
//    Clean warps skip their REDUX pair (cached warp candidate).
//    Distance = fma(dz,dz, fma(dx,dx, dy*dy))  [validated R5]
//    Tie-break: min (orig_idx<<14|pos) == first original index.
// ============================================================
__global__ void __launch_bounds__(512, 1)
fps_kernel(const float* __restrict__ p)
{
    extern __shared__ float sm[];
    // xy4[(k<<9)+c] = (x_{2k}, y_{2k}, x_{2k+1}, y_{2k+1}) for chunk c   (128KB)
    // z2 [(k<<9)+c] = (z_{2k}, z_{2k+1})                                  (64KB)
    float4* xy4 = reinterpret_cast<float4*>(sm);
    float2* z2  = reinterpret_cast<float2*>(sm + 2 * NPTS);
    __shared__ unsigned svb[2][16], spk[2][16];

    int tid = threadIdx.x, lane = tid & 31, wid = tid >> 5;

    // scatter-load into paired layout (element-wise, no RMW races)
    {
        float* xyf = sm;
        float* zf  = sm + 2 * NPTS;
        for (int i = tid; i < NPTS; i += 512) {
            int s = i & 31, c = i >> 5;
            int pbase = (((s >> 1) << 9) + c);
            xyf[pbase * 4 + (s & 1) * 2 + 0] = g_sx[i];
            xyf[pbase * 4 + (s & 1) * 2 + 1] = g_sy[i];
            zf[pbase * 2 + (s & 1)]          = g_sz[i];
        }
    }
    unsigned npack[32];   // ~((orig<<14)|pos): max(~pack) == min(pack)
    #pragma unroll
    for (int s = 0; s < 32; s++)
        npack[s] = ~g_sopack[(tid << 5) + s];

    if (tid == 0) g_idx[0] = 0;
    __syncthreads();

    // chunk bbox over own 32 points
    float bxn = 1e30f, byn = 1e30f, bzn = 1e30f;
    float bxm = -1e30f, bym = -1e30f, bzm = -1e30f;
    #pragma unroll
    for (int k = 0; k < 16; k++) {
        float4 v = xy4[(k << 9) + tid];
        float2 zz = z2[(k << 9) + tid];
        bxn = fminf(bxn, fminf(v.x, v.z)); bxm = fmaxf(bxm, fmaxf(v.x, v.z));
        byn = fminf(byn, fminf(v.y, v.w)); bym = fmaxf(bym, fmaxf(v.y, v.w));
        bzn = fminf(bzn, fminf(zz.x, zz.y)); bzm = fmaxf(bzm, fmaxf(zz.x, zz.y));
    }

    float dd[32];
    #pragma unroll
    for (int s = 0; s < 32; s++) dd[s] = 1e10f;

    float    cv = 1e10f;          // cached chunk max (forces compute at t=1)
    unsigned cnp = 0u;            // cached chunk winner ~pack
    unsigned wm = 0u, wp = 0u;    // cached warp candidate (set at t=1: all dirty)

    float lx = p[0], ly = p[1], lz = p[2];

    for (int t = 1; t < MTOT; ++t) {
        int buf = t & 1;

        // bbox lower bound on squared distance to new point
        float ax = fmaxf(fmaxf(bxn - lx, lx - bxm), 0.f);
        float ay = fmaxf(fmaxf(byn - ly, ly - bym), 0.f);
        float az = fmaxf(fmaxf(bzn - lz, lz - bzm), 0.f);
        float lb = __fmaf_rn(az, az, __fmaf_rn(ay, ay, ax * ax));
        bool dirty = !(lb * 0.9999f >= cv);

        if (dirty) {
            // recompute chunk: exact dd update + u64-key argmax, 2 accumulators
            unsigned long long k0 = 0ull, k1 = 0ull;
            #pragma unroll
            for (int k = 0; k < 16; k++) {
                float4 v = xy4[(k << 9) + tid];
                float2 zz = z2[(k << 9) + tid];
                int s = k << 1;
                {
                    float dx = __fsub_rn(v.x, lx);
                    float dy = __fsub_rn(v.y, ly);
                    float dz = __fsub_rn(zz.x, lz);
                    float d  = __fmaf_rn(dz, dz, __fmaf_rn(dx, dx, __fmul_rn(dy, dy)));
                    float nd = fminf(dd[s], d);
                    dd[s] = nd;
                    unsigned long long nk =
                        ((unsigned long long)__float_as_uint(nd) << 32) | npack[s];
                    if (nk > k0) k0 = nk;
                }
                {
                    float dx = __fsub_rn(v.z, lx);
                    float dy = __fsub_rn(v.w, ly);
                    float dz = __fsub_rn(zz.y, lz);
                    float d  = __fmaf_rn(dz, dz, __fmaf_rn(dx, dx, __fmul_rn(dy, dy)));
                    float nd = fminf(dd[s + 1], d);
                    dd[s + 1] = nd;
                    unsigned long long nk =
                        ((unsigned long long)__float_as_uint(nd) << 32) | npack[s + 1];
                    if (nk > k1) k1 = nk;
                }
            }
            unsigned long long ck = (k0 > k1) ? k0 : k1;
            cv  = __uint_as_float((unsigned)(ck >> 32));
            cnp = (unsigned)ck;
        }

        // warp argmax via redux — skipped entirely if warp is clean
        unsigned mball = __ballot_sync(0xffffffffu, dirty);
        if (mball) {
            unsigned cb = __float_as_uint(cv);
            wm = __reduce_max_sync(0xffffffffu, cb);
            unsigned cand = (cb == wm) ? cnp : 0u;       // ~pack; max == min pack
            wp = __reduce_max_sync(0xffffffffu, cand);
        }
        if (lane == 0) { svb[buf][wid] = wm; spk[buf][wid] = wp; }
        __syncthreads();

        // all warps redundantly reduce the 16 warp results
        unsigned v  = svb[buf][lane & 15];
        unsigned pk = spk[buf][lane & 15];
        unsigned gm = __reduce_max_sync(0xffffffffu, v);
        unsigned c2 = (v == gm) ? pk : 0u;
        unsigned gp = __reduce_max_sync(0xffffffffu, c2);
        unsigned pack = ~gp;                             // (orig<<14)|pos
        int pos = (int)(pack & 16383u);
        int s = pos & 31, c = pos >> 5;
        int pb = ((s >> 1) << 9) + c;
        float4 w4 = xy4[pb];
        float2 wz = z2[pb];
        if (s & 1) { lx = w4.z; ly = w4.w; lz = wz.y; }
        else       { lx = w4.x; ly = w4.y; lz = wz.x; }
        if (tid == 0) g_idx[t] = (int)(pack >> 14);
    }
}

// ============================================================
// 2. Gather sampled coordinates + n_o scalars into output
// ============================================================
__global__ void gather_kernel(const float* __restrict__ p, float* __restrict__ out)
{
    int e = blockIdx.x * blockDim.x + threadIdx.x;
    if (e < MTOT * 3) {
        int q = e / 3, d = e - 3 * q;
        float v = p[g_idx[q] * 3 + d];
        int pos = (q < M1) ? (OFF_NP1 + e) : (OFF_NP2 + (e - M1 * 3));
        out[pos] = v;
    } else if (e == MTOT * 3) {
        out[OFF_NO1] = 4096.0f;
    } else if (e == MTOT * 3 + 1) {
        out[OFF_NO2] = 4096.0f;
    }
}

// ============================================================
// 3. KNN — thread-per-query, SMEM point tiles (broadcast reads),
//    per-thread sorted top-16
// ============================================================
__global__ void __launch_bounds__(128, 8)
knn_kernel(const float* __restrict__ p)
{
    __shared__ float4 tile[2048];   // 32 KB
    int tid = threadIdx.x;
    int qid = blockIdx.x * 128 + tid;
    int qi = g_idx[qid];
    float qx = p[3 * qi], qy = p[3 * qi + 1], qz = p[3 * qi + 2];
    float qq = qx * qx + qy * qy + qz * qz;

    float bd[16]; int bn[16];
    #pragma unroll
    for (int i = 0; i < 16; i++) { bd[i] = 3.4e38f; bn[i] = 0; }

    for (int tb = 0; tb < 8; tb++) {
        for (int i = tid; i < 2048; i += 128) {
            int g = tb * 2048 + i;
            float x = p[3 * g], y = p[3 * g + 1], z = p[3 * g + 2];
            tile[i] = make_float4(x, y, z, x * x + y * y + z * z);
        }
        __syncthreads();
        for (int j = 0; j < 2048; j++) {
            float4 t = tile[j];
            float dot = fmaf(qx, t.x, fmaf(qy, t.y, qz * t.z));
            float d = fmaf(-2.0f, dot, qq) + t.w;
            if (d < bd[15]) {
                int g = tb * 2048 + j;
                int k = 15;
                while (k > 0 && bd[k - 1] > d) {
                    bd[k] = bd[k - 1]; bn[k] = bn[k - 1]; --k;
                }
                bd[k] = d; bn[k] = g;
            }
        }
        __syncthreads();
    }
    #pragma unroll
    for (int i = 0; i < 16; i++) g_knn[qid * 16 + i] = bn[i];
}

// ============================================================
// 4. Grouped feature build + linear (67 -> 128), h to global
//    R15: f stored transposed f[k][s] -> inner loop does
//    4x LDS.128 + 16 FFMA + 1 LDG per k (was 16 scalar LDS).
// ============================================================
__global__ void __launch_bounds__(128, 8)
mlp_kernel(const float* __restrict__ p, const float* __restrict__ x,
           const float* __restrict__ W)
{
    __shared__ float f[CF * 16];    // [k][s]
    __shared__ int   sn[16];
    __shared__ float qc[3];
    int tid = threadIdx.x, q = blockIdx.x;
    if (tid < 16) sn[tid] = g_knn[q * 16 + tid];
    if (tid < 3)  qc[tid] = p[g_idx[q] * 3 + tid];
    __syncthreads();
    for (int e = tid; e < CF * 16; e += 128) {
        int k = e >> 4, s = e & 15;
        int n = sn[s];
        float v = (k < 3) ? (p[n * 3 + k] - qc[k]) : x[n * 64 + (k - 3)];
        f[e] = v;
    }
    __syncthreads();
    float acc[16];
    #pragma unroll
    for (int s = 0; s < 16; s++) acc[s] = 0.f;
    int c = tid;
    const float4* f4 = reinterpret_cast<const float4*>(f);
    for (int k = 0; k < CF; k++) {
        float wv = W[k * 128 + c];
        float4 a = f4[k * 4 + 0];
        float4 b = f4[k * 4 + 1];
        float4 d = f4[k * 4 + 2];
        float4 e = f4[k * 4 + 3];
        acc[0]  = fmaf(a.x, wv, acc[0]);  acc[1]  = fmaf(a.y, wv, acc[1]);
        acc[2]  = fmaf(a.z, wv, acc[2]);  acc[3]  = fmaf(a.w, wv, acc[3]);
        acc[4]  = fmaf(b.x, wv, acc[4]);  acc[5]  = fmaf(b.y, wv, acc[5]);
        acc[6]  = fmaf(b.z, wv, acc[6]);  acc[7]  = fmaf(b.w, wv, acc[7]);
        acc[8]  = fmaf(d.x, wv, acc[8]);  acc[9]  = fmaf(d.y, wv, acc[9]);
        acc[10] = fmaf(d.z, wv, acc[10]); acc[11] = fmaf(d.w, wv, acc[11]);
        acc[12] = fmaf(e.x, wv, acc[12]); acc[13] = fmaf(e.y, wv, acc[13]);
        acc[14] = fmaf(e.z, wv, acc[14]); acc[15] = fmaf(e.w, wv, acc[15]);
    }
    #pragma unroll
    for (int s = 0; s < 16; s++)
        g_h[((size_t)q * 16 + s) * 128 + c] = acc[s];
}

// ============================================================
// 5a. BN partial sums — coalesced float4 reads, fixed-order reduce
// ============================================================
__global__ void __launch_bounds__(256, 4)
stats_part_kernel()
{
    __shared__ float sb1[1024], sb2[1024];
    int tid = threadIdx.x;
    const float* base = g_h + (size_t)blockIdx.x * 131072;

    float s1[4] = {0.f, 0.f, 0.f, 0.f};
    float s2[4] = {0.f, 0.f, 0.f, 0.f};
    #pragma unroll 4
    for (int it = 0; it < 128; it++) {
        const float4 v4 = *reinterpret_cast<const float4*>(base + it * 1024 + tid * 4);
        s1[0] += v4.x; s2[0] = fmaf(v4.x, v4.x, s2[0]);
        s1[1] += v4.y; s2[1] = fmaf(v4.y, v4.y, s2[1]);
        s1[2] += v4.z; s2[2] = fmaf(v4.z, v4.z, s2[2]);
        s1[3] += v4.w; s2[3] = fmaf(v4.w, v4.w, s2[3]);
    }
    #pragma unroll
    for (int k = 0; k < 4; k++) { sb1[tid * 4 + k] = s1[k]; sb2[tid * 4 + k] = s2[k]; }
    __syncthreads();
    if (tid < 32) {
        #pragma unroll
        for (int k = 0; k < 4; k++) {
            float a1 = 0.f, a2 = 0.f;
            #pragma unroll
            for (int j = 0; j < 8; j++) {
                a1 += sb1[(tid + 32 * j) * 4 + k];
                a2 += sb2[(tid + 32 * j) * 4 + k];
            }
            int c = (tid * 4 + k) & 127;
            g_part1[blockIdx.x * 128 + c] = a1;
            g_part2[blockIdx.x * 128 + c] = a2;
        }
    }
}

// ============================================================
// 5b. BN finalize — 256 threads = (half, channel) pairs
// ============================================================
__global__ void stats_fin_kernel(const float* __restrict__ gamma,
                                 const float* __restrict__ beta)
{
    int tid = threadIdx.x;          // 0..255
    int half = tid >> 7, c = tid & 127;
    float s1 = 0.f, s2 = 0.f;
    for (int j = 0; j < 64; j++) {
        s1 += g_part1[(half * 64 + j) * 128 + c];
        s2 += g_part2[(half * 64 + j) * 128 + c];
    }
    float mean = s1 * (1.f / 65536.f);
    float var  = s2 * (1.f / 65536.f) - mean * mean;
    float sc = rsqrtf(var + 1e-5f) * gamma[c];
    g_scale[tid] = sc;
    g_shift[tid] = beta[c] - mean * sc;
}

// ============================================================
// 6. BN apply + ReLU + max-pool over nsample, write x1/x2
// ============================================================
__global__ void __launch_bounds__(128, 8)
pool_kernel(float* __restrict__ out)
{
    int q = blockIdx.x, c = threadIdx.x;
    int half = (q >= M1);
    float sc = g_scale[half * 128 + c];
    float sh = g_shift[half * 128 + c];
    float m = 0.f;   // relu floor; max over 16 relu outputs >= 0
    const float* hb = g_h + ((size_t)q * 16) * 128 + c;
    #pragma unroll
    for (int s = 0; s < 16; s++) {
        float v = fmaf(hb[s * 128], sc, sh);
        v = fmaxf(v, 0.f);
        m = fmaxf(m, v);
    }
    int pos = (q < M1) ? (OFF_X1 + q * 128 + c)
                       : (OFF_X2 + (q - M1) * 128 + c);
    out[pos] = m;
}

// ============================================================
extern "C" void kernel_launch(void* const* d_in, const int* in_sizes, int n_in,
                              void* d_out, int out_size)
{
    const float* p     = (const float*)d_in[0];
    const float* x     = (const float*)d_in[1];
    // d_in[2] = o (int32, unused: single batch)
    const float* W     = (const float*)d_in[3];
    const float* gamma = (const float*)d_in[4];
    const float* beta  = (const float*)d_in[5];
    float* out = (float*)d_out;

    cudaFuncSetAttribute(sort_kernel,
                         cudaFuncAttributeMaxDynamicSharedMemorySize,
                         NPTS * sizeof(unsigned long long));
    cudaFuncSetAttribute(fps_kernel,
                         cudaFuncAttributeMaxDynamicSharedMemorySize,
                         NPTS * 3 * sizeof(float));

    sort_kernel<<<1, 1024, NPTS * sizeof(unsigned long long)>>>(p);
    dummy_kernel<<<1, 32>>>();   // keep ncu -s 5 window on fps_kernel
    dummy_kernel<<<1, 32>>>();
    fps_kernel<<<1, 512, NPTS * 3 * sizeof(float)>>>(p);
    gather_kernel<<<(MTOT * 3 + 2 + 255) / 256, 256>>>(p, out);
    knn_kernel<<<64, 128>>>(p);
    mlp_kernel<<<MTOT, 128>>>(p, x, W);
    stats_part_kernel<<<128, 256>>>();
    stats_fin_kernel<<<1, 256>>>(gamma, beta);
    pool_kernel<<<MTOT, 128>>>(out);
}

// round 16
// speedup vs baseline: 1.0637x; 1.0637x over previous
#include <cuda_runtime.h>

#define NPTS 16384
#define MTOT 8192
#define M1   4096
#define CIN  64
#define COUT 128
#define KNNK 16
#define CF   67   // 3 + 64

// ---- output layout (floats) ----
#define OFF_NP1 0
#define OFF_X1  12288
#define OFF_NO1 536576
#define OFF_NP2 536577
#define OFF_X2  548865
#define OFF_NO2 1073153

// ---- device scratch (no allocations allowed) ----
__device__ int   g_idx[MTOT];
__device__ int   g_knn[MTOT * KNNK];
__device__ float g_h[(size_t)MTOT * KNNK * COUT];   // 64 MB
__device__ float g_scale[2 * COUT];
__device__ float g_shift[2 * COUT];
// sorted point arrays (Morton order)
__device__ float g_sx[NPTS];
__device__ float g_sy[NPTS];
__device__ float g_sz[NPTS];
__device__ unsigned g_sopack[NPTS];   // (orig_idx << 14) | sorted_pos
// BN partial sums
__device__ float g_part1[128 * 128];
__device__ float g_part2[128 * 128];

// ============================================================
// no-op dummy — keeps the ncu -s 5 capture window on fps_kernel
// ============================================================
__global__ void dummy_kernel() {}

// ============================================================
// 0. Morton sort — single CTA bitonic sort of (code<<14 | idx)
// ============================================================
__device__ __forceinline__ unsigned expand10(unsigned v)
{
    v &= 1023u;
    v = (v | (v << 16)) & 0x030000FFu;
    v = (v | (v << 8))  & 0x0300F00Fu;
    v = (v | (v << 4))  & 0x030C30C3u;
    v = (v | (v << 2))  & 0x09249249u;
    return v;
}

__global__ void __launch_bounds__(1024, 1)
sort_kernel(const float* __restrict__ p)
{
    extern __shared__ unsigned long long key[];   // 16384 * 8B = 128KB
    __shared__ float rmin[3][32], rmax[3][32];
    __shared__ float bb[6];

    int tid = threadIdx.x, lane = tid & 31, wid = tid >> 5;

    float mn[3] = {1e30f, 1e30f, 1e30f};
    float mx[3] = {-1e30f, -1e30f, -1e30f};
    for (int i = tid; i < NPTS; i += 1024) {
        float c[3] = {p[3 * i], p[3 * i + 1], p[3 * i + 2]};
        #pragma unroll
        for (int d = 0; d < 3; d++) {
            mn[d] = fminf(mn[d], c[d]);
            mx[d] = fmaxf(mx[d], c[d]);
        }
    }
    #pragma unroll
    for (int off = 16; off > 0; off >>= 1) {
        #pragma unroll
        for (int d = 0; d < 3; d++) {
            mn[d] = fminf(mn[d], __shfl_xor_sync(0xffffffffu, mn[d], off));
            mx[d] = fmaxf(mx[d], __shfl_xor_sync(0xffffffffu, mx[d], off));
        }
    }
    if (lane == 0) {
        #pragma unroll
        for (int d = 0; d < 3; d++) { rmin[d][wid] = mn[d]; rmax[d][wid] = mx[d]; }
    }
    __syncthreads();
    if (tid < 32) {
        #pragma unroll
        for (int d = 0; d < 3; d++) { mn[d] = rmin[d][tid]; mx[d] = rmax[d][tid]; }
        #pragma unroll
        for (int off = 16; off > 0; off >>= 1) {
            #pragma unroll
            for (int d = 0; d < 3; d++) {
                mn[d] = fminf(mn[d], __shfl_xor_sync(0xffffffffu, mn[d], off));
                mx[d] = fmaxf(mx[d], __shfl_xor_sync(0xffffffffu, mx[d], off));
            }
        }
        if (tid == 0) {
            #pragma unroll
            for (int d = 0; d < 3; d++) { bb[d] = mn[d]; bb[3 + d] = mx[d]; }
        }
    }
    __syncthreads();

    float ox = bb[0], oy = bb[1], oz = bb[2];
    float scx = 1023.0f / fmaxf(bb[3] - bb[0], 1e-20f);
    float scy = 1023.0f / fmaxf(bb[4] - bb[1], 1e-20f);
    float scz = 1023.0f / fmaxf(bb[5] - bb[2], 1e-20f);

    for (int i = tid; i < NPTS; i += 1024) {
        unsigned xi = (unsigned)fminf(fmaxf((p[3 * i]     - ox) * scx, 0.f), 1023.f);
        unsigned yi = (unsigned)fminf(fmaxf((p[3 * i + 1] - oy) * scy, 0.f), 1023.f);
        unsigned zi = (unsigned)fminf(fmaxf((p[3 * i + 2] - oz) * scz, 0.f), 1023.f);
        unsigned code = (expand10(xi) << 2) | (expand10(yi) << 1) | expand10(zi);
        key[i] = ((unsigned long long)code << 14) | (unsigned)i;
    }
    __syncthreads();

    // bitonic sort
    for (int k = 2; k <= NPTS; k <<= 1) {
        for (int j = k >> 1; j > 0; j >>= 1) {
            for (int t = tid; t < NPTS; t += 1024) {
                int ixj = t ^ j;
                if (ixj > t) {
                    bool up = ((t & k) == 0);
                    unsigned long long a = key[t], b = key[ixj];
                    if ((a > b) == up) { key[t] = b; key[ixj] = a; }
                }
            }
            __syncthreads();
        }
    }

    for (int i = tid; i < NPTS; i += 1024) {
        int oi = (int)(key[i] & 16383ull);
        g_sx[i] = p[3 * oi];
        g_sy[i] = p[3 * oi + 1];
        g_sz[i] = p[3 * oi + 2];
        g_sopack[i] = ((unsigned)oi << 14) | (unsigned)i;
    }
}

// ============================================================
// 1. FPS — single CTA, 1024 threads, ONE 16-point Morton chunk
//    per thread, transposed SMEM (conflict-free), bbox skipping,
//    u64-key dirty-pass argmax (validated R14).
//    Smaller chunks: shorter dirty passes, finer skip granularity,
//    dirty work spread over 2x warps.
//    Distance = fma(dz,dz, fma(dx,dx, dy*dy))  [validated R5]
//    Tie-break: min (orig_idx<<14|pos) == first original index
//    (u64 max == max value, tie -> max ~pack == min pack).
// ============================================================
__global__ void __launch_bounds__(1024, 1)
fps_kernel(const float* __restrict__ p)
{
    extern __shared__ float sm[];
    float2* sxy = reinterpret_cast<float2*>(sm);   // [16 slots][1024 chunks]
    float*  szz = sm + 2 * NPTS;
    __shared__ unsigned svb[2][32], spk[2][32];

    int tid = threadIdx.x, lane = tid & 31, wid = tid >> 5;

    for (int i = tid; i < NPTS; i += 1024) {
        int a = ((i & 15) << 10) | (i >> 4);
        sxy[a] = make_float2(g_sx[i], g_sy[i]);
        szz[a] = g_sz[i];
    }
    unsigned npack[16];   // ~((orig<<14)|pos): max(~pack) == min(pack)
    #pragma unroll
    for (int s = 0; s < 16; s++)
        npack[s] = ~g_sopack[(tid << 4) + s];

    if (tid == 0) g_idx[0] = 0;
    __syncthreads();

    // chunk bbox over own 16 points (lane-contiguous loads)
    float bxn = 1e30f, byn = 1e30f, bzn = 1e30f;
    float bxm = -1e30f, bym = -1e30f, bzm = -1e30f;
    #pragma unroll
    for (int s = 0; s < 16; s++) {
        float2 xy = sxy[(s << 10) + tid];
        float z = szz[(s << 10) + tid];
        bxn = fminf(bxn, xy.x); bxm = fmaxf(bxm, xy.x);
        byn = fminf(byn, xy.y); bym = fmaxf(bym, xy.y);
        bzn = fminf(bzn, z);    bzm = fmaxf(bzm, z);
    }

    float dd[16];
    #pragma unroll
    for (int s = 0; s < 16; s++) dd[s] = 1e10f;

    float    cv = 1e10f;          // cached chunk max (forces compute at t=1)
    unsigned cnp = 0u;            // cached chunk winner ~pack

    float lx = p[0], ly = p[1], lz = p[2];

    for (int t = 1; t < MTOT; ++t) {
        int buf = t & 1;

        // bbox lower bound on squared distance to new point
        float ax = fmaxf(fmaxf(bxn - lx, lx - bxm), 0.f);
        float ay = fmaxf(fmaxf(byn - ly, ly - bym), 0.f);
        float az = fmaxf(fmaxf(bzn - lz, lz - bzm), 0.f);
        float lb = __fmaf_rn(az, az, __fmaf_rn(ay, ay, ax * ax));

        if (!(lb * 0.9999f >= cv)) {
            // recompute chunk: exact dd update + u64-key argmax, 2 accumulators
            unsigned long long k0 = 0ull, k1 = 0ull;
            #pragma unroll
            for (int s = 0; s < 16; s += 2) {
                {
                    int a = (s << 10) + tid;
                    float2 xy = sxy[a];
                    float dx = __fsub_rn(xy.x, lx);
                    float dy = __fsub_rn(xy.y, ly);
                    float dz = __fsub_rn(szz[a], lz);
                    float d  = __fmaf_rn(dz, dz, __fmaf_rn(dx, dx, __fmul_rn(dy, dy)));
                    float nd = fminf(dd[s], d);
                    dd[s] = nd;
                    unsigned long long nk =
                        ((unsigned long long)__float_as_uint(nd) << 32) | npack[s];
                    if (nk > k0) k0 = nk;
                }
                {
                    int a = ((s + 1) << 10) + tid;
                    float2 xy = sxy[a];
                    float dx = __fsub_rn(xy.x, lx);
                    float dy = __fsub_rn(xy.y, ly);
                    float dz = __fsub_rn(szz[a], lz);
                    float d  = __fmaf_rn(dz, dz, __fmaf_rn(dx, dx, __fmul_rn(dy, dy)));
                    float nd = fminf(dd[s + 1], d);
                    dd[s + 1] = nd;
                    unsigned long long nk =
                        ((unsigned long long)__float_as_uint(nd) << 32) | npack[s + 1];
                    if (nk > k1) k1 = nk;
                }
            }
            unsigned long long ck = (k0 > k1) ? k0 : k1;
            cv  = __uint_as_float((unsigned)(ck >> 32));
            cnp = (unsigned)ck;
        }

        // warp argmax via redux (d >= 0 so u32 bit order == float order)
        unsigned cb = __float_as_uint(cv);
        unsigned wm = __reduce_max_sync(0xffffffffu, cb);
        unsigned cand = (cb == wm) ? cnp : 0u;           // ~pack; max == min pack
        unsigned wp = __reduce_max_sync(0xffffffffu, cand);
        if (lane == 0) { svb[buf][wid] = wm; spk[buf][wid] = wp; }
        __syncthreads();

        // all warps redundantly reduce the 32 warp results
        unsigned v  = svb[buf][lane];
        unsigned pk = spk[buf][lane];
        unsigned gm = __reduce_max_sync(0xffffffffu, v);
        unsigned c2 = (v == gm) ? pk : 0u;
        unsigned gp = __reduce_max_sync(0xffffffffu, c2);
        unsigned pack = ~gp;                             // (orig<<14)|pos
        int pos = (int)(pack & 16383u);
        int ad  = ((pos & 15) << 10) | (pos >> 4);
        float2 wxy = sxy[ad];
        lx = wxy.x; ly = wxy.y; lz = szz[ad];
        if (tid == 0) g_idx[t] = (int)(pack >> 14);
    }
}

// ============================================================
// 2. Gather sampled coordinates + n_o scalars into output
// ============================================================
__global__ void gather_kernel(const float* __restrict__ p, float* __restrict__ out)
{
    int e = blockIdx.x * blockDim.x + threadIdx.x;
    if (e < MTOT * 3) {
        int q = e / 3, d = e - 3 * q;
        float v = p[g_idx[q] * 3 + d];
        int pos = (q < M1) ? (OFF_NP1 + e) : (OFF_NP2 + (e - M1 * 3));
        out[pos] = v;
    } else if (e == MTOT * 3) {
        out[OFF_NO1] = 4096.0f;
    } else if (e == MTOT * 3 + 1) {
        out[OFF_NO2] = 4096.0f;
    }
}

// ============================================================
// 3. KNN — thread-per-query, SMEM point tiles (broadcast reads),
//    per-thread sorted top-16
// ============================================================
__global__ void __launch_bounds__(128, 8)
knn_kernel(const float* __restrict__ p)
{
    __shared__ float4 tile[2048];   // 32 KB
    int tid = threadIdx.x;
    int qid = blockIdx.x * 128 + tid;
    int qi = g_idx[qid];
    float qx = p[3 * qi], qy = p[3 * qi + 1], qz = p[3 * qi + 2];
    float qq = qx * qx + qy * qy + qz * qz;

    float bd[16]; int bn[16];
    #pragma unroll
    for (int i = 0; i < 16; i++) { bd[i] = 3.4e38f; bn[i] = 0; }

    for (int tb = 0; tb < 8; tb++) {
        for (int i = tid; i < 2048; i += 128) {
            int g = tb * 2048 + i;
            float x = p[3 * g], y = p[3 * g + 1], z = p[3 * g + 2];
            tile[i] = make_float4(x, y, z, x * x + y * y + z * z);
        }
        __syncthreads();
        for (int j = 0; j < 2048; j++) {
            float4 t = tile[j];
            float dot = fmaf(qx, t.x, fmaf(qy, t.y, qz * t.z));
            float d = fmaf(-2.0f, dot, qq) + t.w;
            if (d < bd[15]) {
                int g = tb * 2048 + j;
                int k = 15;
                while (k > 0 && bd[k - 1] > d) {
                    bd[k] = bd[k - 1]; bn[k] = bn[k - 1]; --k;
                }
                bd[k] = d; bn[k] = g;
            }
        }
        __syncthreads();
    }
    #pragma unroll
    for (int i = 0; i < 16; i++) g_knn[qid * 16 + i] = bn[i];
}

// ============================================================
// 4. Grouped feature build + linear (67 -> 128), h to global
// ============================================================
__global__ void __launch_bounds__(128, 8)
mlp_kernel(const float* __restrict__ p, const float* __restrict__ x,
           const float* __restrict__ W)
{
    __shared__ float f[16 * 68];
    __shared__ int   sn[16];
    __shared__ float qc[3];
    int tid = threadIdx.x, q = blockIdx.x;
    if (tid < 16) sn[tid] = g_knn[q * 16 + tid];
    if (tid < 3)  qc[tid] = p[g_idx[q] * 3 + tid];
    __syncthreads();
    for (int e = tid; e < 16 * CF; e += 128) {
        int s = e / CF, k = e - CF * s;
        int n = sn[s];
        float v = (k < 3) ? (p[n * 3 + k] - qc[k]) : x[n * 64 + (k - 3)];
        f[s * 68 + k] = v;
    }
    __syncthreads();
    float acc[16];
    #pragma unroll
    for (int s = 0; s < 16; s++) acc[s] = 0.f;
    int c = tid;
    for (int k = 0; k < CF; k++) {
        float wv = W[k * 128 + c];
        #pragma unroll
        for (int s = 0; s < 16; s++)
            acc[s] = fmaf(f[s * 68 + k], wv, acc[s]);
    }
    #pragma unroll
    for (int s = 0; s < 16; s++)
        g_h[((size_t)q * 16 + s) * 128 + c] = acc[s];
}

// ============================================================
// 5a. BN partial sums — coalesced float4 reads, fixed-order reduce
// ============================================================
__global__ void __launch_bounds__(256, 4)
stats_part_kernel()
{
    __shared__ float sb1[1024], sb2[1024];
    int tid = threadIdx.x;
    const float* base = g_h + (size_t)blockIdx.x * 131072;

    float s1[4] = {0.f, 0.f, 0.f, 0.f};
    float s2[4] = {0.f, 0.f, 0.f, 0.f};
    #pragma unroll 4
    for (int it = 0; it < 128; it++) {
        const float4 v4 = *reinterpret_cast<const float4*>(base + it * 1024 + tid * 4);
        s1[0] += v4.x; s2[0] = fmaf(v4.x, v4.x, s2[0]);
        s1[1] += v4.y; s2[1] = fmaf(v4.y, v4.y, s2[1]);
        s1[2] += v4.z; s2[2] = fmaf(v4.z, v4.z, s2[2]);
        s1[3] += v4.w; s2[3] = fmaf(v4.w, v4.w, s2[3]);
    }
    #pragma unroll
    for (int k = 0; k < 4; k++) { sb1[tid * 4 + k] = s1[k]; sb2[tid * 4 + k] = s2[k]; }
    __syncthreads();
    if (tid < 32) {
        #pragma unroll
        for (int k = 0; k < 4; k++) {
            float a1 = 0.f, a2 = 0.f;
            #pragma unroll
            for (int j = 0; j < 8; j++) {
                a1 += sb1[(tid + 32 * j) * 4 + k];
                a2 += sb2[(tid + 32 * j) * 4 + k];
            }
            int c = (tid * 4 + k) & 127;
            g_part1[blockIdx.x * 128 + c] = a1;
            g_part2[blockIdx.x * 128 + c] = a2;
        }
    }
}

// ============================================================
// 5b. BN finalize — 256 threads = (half, channel) pairs
// ============================================================
__global__ void stats_fin_kernel(const float* __restrict__ gamma,
                                 const float* __restrict__ beta)
{
    int tid = threadIdx.x;          // 0..255
    int half = tid >> 7, c = tid & 127;
    float s1 = 0.f, s2 = 0.f;
    for (int j = 0; j < 64; j++) {
        s1 += g_part1[(half * 64 + j) * 128 + c];
        s2 += g_part2[(half * 64 + j) * 128 + c];
    }
    float mean = s1 * (1.f / 65536.f);
    float var  = s2 * (1.f / 65536.f) - mean * mean;
    float sc = rsqrtf(var + 1e-5f) * gamma[c];
    g_scale[tid] = sc;
    g_shift[tid] = beta[c] - mean * sc;
}

// ============================================================
// 6. BN apply + ReLU + max-pool over nsample, write x1/x2
// ============================================================
__global__ void __launch_bounds__(128, 8)
pool_kernel(float* __restrict__ out)
{
    int q = blockIdx.x, c = threadIdx.x;
    int half = (q >= M1);
    float sc = g_scale[half * 128 + c];
    float sh = g_shift[half * 128 + c];
    float m = 0.f;   // relu floor; max over 16 relu outputs >= 0
    const float* hb = g_h + ((size_t)q * 16) * 128 + c;
    #pragma unroll
    for (int s = 0; s < 16; s++) {
        float v = fmaf(hb[s * 128], sc, sh);
        v = fmaxf(v, 0.f);
        m = fmaxf(m, v);
    }
    int pos = (q < M1) ? (OFF_X1 + q * 128 + c)
                       : (OFF_X2 + (q - M1) * 128 + c);
    out[pos] = m;
}

// ============================================================
extern "C" void kernel_launch(void* const* d_in, const int* in_sizes, int n_in,
                              void* d_out, int out_size)
{
    const float* p     = (const float*)d_in[0];
    const float* x     = (const float*)d_in[1];
    // d_in[2] = o (int32, unused: single batch)
    const float* W     = (const float*)d_in[3];
    const float* gamma = (const float*)d_in[4];
    const float* beta  = (const float*)d_in[5];
    float* out = (float*)d_out;

    cudaFuncSetAttribute(sort_kernel,
                         cudaFuncAttributeMaxDynamicSharedMemorySize,
                         NPTS * sizeof(unsigned long long));
    cudaFuncSetAttribute(fps_kernel,
                         cudaFuncAttributeMaxDynamicSharedMemorySize,
                         NPTS * 3 * sizeof(float));

    sort_kernel<<<1, 1024, NPTS * sizeof(unsigned long long)>>>(p);
    dummy_kernel<<<1, 32>>>();   // keep ncu -s 5 window on fps_kernel
    dummy_kernel<<<1, 32>>>();
    fps_kernel<<<1, 1024, NPTS * 3 * sizeof(float)>>>(p);
    gather_kernel<<<(MTOT * 3 + 2 + 255) / 256, 256>>>(p, out);
    knn_kernel<<<64, 128>>>(p);
    mlp_kernel<<<MTOT, 128>>>(p, x, W);
    stats_part_kernel<<<128, 256>>>();
    stats_fin_kernel<<<1, 256>>>(gamma, beta);
    pool_kernel<<<MTOT, 128>>>(out);
}